// round 11
// baseline (speedup 1.0000x reference)
#include <cuda_runtime.h>
#include <math.h>

// Problem constants
#define BB 32
#define C3 1024
#define C4 2048
#define CTOT 3072
#define HH 28
#define HW 784
#define H4 14
#define HW4 196
#define LL 9
#define NA 312
#define NC 200

#define GB 16        // batches per group (2 groups)
#define NCK4 8       // l4 channel chunks of 256
#define NCK3 8       // l3 channel chunks of 128

// Output layout (flattened concat of reference return tuple)
#define OFF_ATTR  0
#define OFF_CLASS (BB*NA)                  // 9984
#define OFF_MAPS  (OFF_CLASS + BB*NC)      // 16384
#define OFF_AF    (OFF_MAPS + BB*LL*HW)    // 242176

// Scratch (__device__ globals; no runtime allocation allowed)
__device__ __align__(16) float g_pab4[NCK4 * BB * LL * HW4];  // l4 partial ab, 14x14
__device__ __align__(16) float g_pab3[NCK3 * BB * LL * HW];   // l3 partial ab, 28x28
__device__ __align__(16) float g_mdown[BB * LL * HW4];        // adjoint-downsampled maps
__device__ __align__(16) float g_meanf[BB * CTOT];            // mean features
__device__ float g_asq[LL];

// ---------------------------------------------------------------------------
// Fused ab kernel for one batch group.
// grid.x = 257 blocks of 128 threads:
//   [0,56):    ab4 — 8 chunks x 7 blocks; chunk = 256 l4 channels
//   [56,256):  ab3 — 8 chunks x 25 blocks; chunk = 128 l3 channels
//   256:       asq reduction (sum of conv_w rows)
__global__ void __launch_bounds__(128, 5) k_ab(const float* __restrict__ l3,
                                               const float* __restrict__ l4,
                                               const float* __restrict__ cw,
                                               int b0) {
    __shared__ __align__(16) float w_s[LL * 256];
    int i = blockIdx.x, tid = threadIdx.x;

    if (i < 56) {
        // ---------------- ab4: l4 @ 14x14, 256-channel chunk ----------------
        int ck = i / 7;
        for (int j = tid; j < LL * 256; j += 128)
            w_s[j] = cw[(j >> 8) * CTOT + ck * 256 + (j & 255)];
        __syncthreads();

        int t = (i % 7) * 128 + tid;
        if (t >= GB * 49) return;
        int b = b0 + t / 49;
        int q = (t % 49) * 4;

        const float* src = l4 + ((size_t)b * C4 + (size_t)ck * 256) * HW4 + q;

        float4 acc[LL];
        #pragma unroll
        for (int l = 0; l < LL; l++) acc[l] = make_float4(0.f, 0.f, 0.f, 0.f);

        #pragma unroll 2
        for (int ci = 0; ci < 256; ci += 4) {
            float4 x0 = *(const float4*)(src + (size_t)(ci + 0) * HW4);
            float4 x1 = *(const float4*)(src + (size_t)(ci + 1) * HW4);
            float4 x2 = *(const float4*)(src + (size_t)(ci + 2) * HW4);
            float4 x3 = *(const float4*)(src + (size_t)(ci + 3) * HW4);
            #pragma unroll
            for (int l = 0; l < LL; l++) {
                float4 w = *(const float4*)&w_s[l * 256 + ci];
                acc[l].x = fmaf(w.x, x0.x, acc[l].x);
                acc[l].y = fmaf(w.x, x0.y, acc[l].y);
                acc[l].z = fmaf(w.x, x0.z, acc[l].z);
                acc[l].w = fmaf(w.x, x0.w, acc[l].w);
                acc[l].x = fmaf(w.y, x1.x, acc[l].x);
                acc[l].y = fmaf(w.y, x1.y, acc[l].y);
                acc[l].z = fmaf(w.y, x1.z, acc[l].z);
                acc[l].w = fmaf(w.y, x1.w, acc[l].w);
                acc[l].x = fmaf(w.z, x2.x, acc[l].x);
                acc[l].y = fmaf(w.z, x2.y, acc[l].y);
                acc[l].z = fmaf(w.z, x2.z, acc[l].z);
                acc[l].w = fmaf(w.z, x2.w, acc[l].w);
                acc[l].x = fmaf(w.w, x3.x, acc[l].x);
                acc[l].y = fmaf(w.w, x3.y, acc[l].y);
                acc[l].z = fmaf(w.w, x3.z, acc[l].z);
                acc[l].w = fmaf(w.w, x3.w, acc[l].w);
            }
        }
        #pragma unroll
        for (int l = 0; l < LL; l++)
            *(float4*)&g_pab4[((size_t)(ck * BB + b) * LL + l) * HW4 + q] = acc[l];

    } else if (i < 256) {
        // ---------------- ab3: l3 @ 28x28, 128-channel chunk ----------------
        int j = i - 56;
        int ck = j / 25;
        for (int jj = tid; jj < LL * 128; jj += 128)
            w_s[jj] = cw[(jj >> 7) * CTOT + C4 + ck * 128 + (jj & 127)];
        __syncthreads();

        int t = (j % 25) * 128 + tid;
        if (t >= GB * 196) return;
        int b = b0 + t / 196;
        int p = (t % 196) * 4;

        const float* src = l3 + ((size_t)b * C3 + (size_t)ck * 128) * HW + p;

        float4 acc[LL];
        #pragma unroll
        for (int l = 0; l < LL; l++) acc[l] = make_float4(0.f, 0.f, 0.f, 0.f);

        #pragma unroll 2
        for (int ci = 0; ci < 128; ci += 4) {
            float4 x0 = *(const float4*)(src + (size_t)(ci + 0) * HW);
            float4 x1 = *(const float4*)(src + (size_t)(ci + 1) * HW);
            float4 x2 = *(const float4*)(src + (size_t)(ci + 2) * HW);
            float4 x3 = *(const float4*)(src + (size_t)(ci + 3) * HW);
            #pragma unroll
            for (int l = 0; l < LL; l++) {
                float4 w = *(const float4*)&w_s[l * 128 + ci];
                acc[l].x = fmaf(w.x, x0.x, acc[l].x);
                acc[l].y = fmaf(w.x, x0.y, acc[l].y);
                acc[l].z = fmaf(w.x, x0.z, acc[l].z);
                acc[l].w = fmaf(w.x, x0.w, acc[l].w);
                acc[l].x = fmaf(w.y, x1.x, acc[l].x);
                acc[l].y = fmaf(w.y, x1.y, acc[l].y);
                acc[l].z = fmaf(w.y, x1.z, acc[l].z);
                acc[l].w = fmaf(w.y, x1.w, acc[l].w);
                acc[l].x = fmaf(w.z, x2.x, acc[l].x);
                acc[l].y = fmaf(w.z, x2.y, acc[l].y);
                acc[l].z = fmaf(w.z, x2.z, acc[l].z);
                acc[l].w = fmaf(w.z, x2.w, acc[l].w);
                acc[l].x = fmaf(w.w, x3.x, acc[l].x);
                acc[l].y = fmaf(w.w, x3.y, acc[l].y);
                acc[l].z = fmaf(w.w, x3.z, acc[l].z);
                acc[l].w = fmaf(w.w, x3.w, acc[l].w);
            }
        }
        #pragma unroll
        for (int l = 0; l < LL; l++)
            *(float4*)&g_pab3[((size_t)(ck * BB + b) * LL + l) * HW + p] = acc[l];

    } else {
        // ---------------- asq: a_sq[l] = sum_c conv_w[l][c] -----------------
        for (int l = 0; l < LL; l++) {
            float s = 0.f;
            for (int c = tid; c < CTOT; c += 128) s += cw[l * CTOT + c];
            w_s[tid] = s;
            __syncthreads();
            for (int off = 64; off; off >>= 1) {
                if (tid < off) w_s[tid] += w_s[tid + off];
                __syncthreads();
            }
            if (tid == 0) g_asq[l] = w_s[0];
            __syncthreads();
        }
    }
}

// ---------------------------------------------------------------------------
// Adjoint bilinear weight: contribution of output index y to input index r.
__device__ __forceinline__ float tapw(int y, int r) {
    float f = y * 0.5f - 0.25f;
    int i0 = (int)floorf(f);
    float w1 = f - (float)i0;
    int c0 = max(i0, 0), c1 = min(i0 + 1, H4 - 1);
    float w = 0.f;
    if (c0 == r) w += 1.f - w1;
    if (c1 == r) w += w1;
    return w;
}

// ---------------------------------------------------------------------------
// Per-batch softmax kernel: block = 1 batch, 784 threads.
// Phase A: reduce g_pab4 chunks into smem (14x14 ab4).
// Phase B: per pixel: bilinear + pab3 gather + softmax -> maps (smem + gmem).
// Phase C: adjoint-downsample maps -> g_mdown.
__global__ void k_softmax(float* __restrict__ maps_out, int b0) {
    __shared__ __align__(16) float a4s[LL * HW4];   // 7056 B
    __shared__ __align__(16) float mps[LL * HW];    // 28224 B
    int b = b0 + blockIdx.x;
    int tid = threadIdx.x;

    // Phase A
    for (int idx = tid; idx < LL * HW4; idx += 784) {
        float s = 0.f;
        #pragma unroll
        for (int ck = 0; ck < NCK4; ck++)
            s += g_pab4[((size_t)ck * BB + b) * (LL * HW4) + idx];
        a4s[idx] = s;
    }
    __syncthreads();

    // Phase B (p = tid, exactly 784 pixels)
    {
        int p = tid;
        int y = p / HH, x = p % HH;

        float fy = y * 0.5f - 0.25f;
        int iy = (int)floorf(fy);
        float wy1 = fy - (float)iy;
        float wy0 = 1.f - wy1;
        int y0 = max(iy, 0), y1 = min(iy + 1, H4 - 1);

        float fx = x * 0.5f - 0.25f;
        int ix = (int)floorf(fx);
        float wx1 = fx - (float)ix;
        float wx0 = 1.f - wx1;
        int x0 = max(ix, 0), x1 = min(ix + 1, H4 - 1);

        float logit[LL];
        float mx = -1e30f;
        #pragma unroll
        for (int l = 0; l < LL; l++) {
            const float* a4 = a4s + l * HW4;
            float v = wy0 * (wx0 * a4[y0 * H4 + x0] + wx1 * a4[y0 * H4 + x1])
                    + wy1 * (wx0 * a4[y1 * H4 + x0] + wx1 * a4[y1 * H4 + x1]);
            float s3 = 0.f;
            #pragma unroll
            for (int ck = 0; ck < NCK3; ck++)
                s3 += g_pab3[((size_t)(ck * BB + b) * LL + l) * HW + p];
            float lg = 2.f * (v + s3) - g_asq[l];
            logit[l] = lg;
            mx = fmaxf(mx, lg);
        }
        float e[LL], den = 0.f;
        #pragma unroll
        for (int l = 0; l < LL; l++) { e[l] = __expf(logit[l] - mx); den += e[l]; }
        float inv = 1.f / den;
        #pragma unroll
        for (int l = 0; l < LL; l++) {
            float m = e[l] * inv;
            mps[l * HW + p] = m;
            maps_out[(size_t)(b * LL + l) * HW + p] = m;
        }
    }
    __syncthreads();

    // Phase C: mdown
    for (int t = tid; t < LL * HW4; t += 784) {
        int l = t / HW4, q = t % HW4;
        int r = q / H4, c = q % H4;
        const float* mp = mps + l * HW;
        int ylo = max(0, 2 * r - 1), yhi = min(HH - 1, 2 * r + 2);
        int xlo = max(0, 2 * c - 1), xhi = min(HH - 1, 2 * c + 2);
        float s = 0.f;
        for (int y = ylo; y <= yhi; y++) {
            float wy = tapw(y, r);
            for (int x = xlo; x <= xhi; x++)
                s += wy * tapw(x, c) * mp[y * HH + x];
        }
        g_mdown[(size_t)b * LL * HW4 + t] = s;
    }
}

// ---------------------------------------------------------------------------
// Fused feature kernel for one batch group. 128 threads (4 warps, 4 ch/warp).
// grid.x = 3072: [0,1024) feat3 (b-local = i/64, ct = i%64);
//                [1024,3072) feat4 (j = i-1024, b-local = j/128, ct = j%128).
__global__ void __launch_bounds__(128, 5)
k_feat(const float* __restrict__ l3, const float* __restrict__ l4,
       const float* __restrict__ maps_out, const float* __restrict__ modulation,
       float* __restrict__ af_out, int b0) {
    __shared__ __align__(16) float mp_s[LL * HW];   // 28224 B (feat4 uses first 7056)
    int i = blockIdx.x, tid = threadIdx.x;
    int warp = tid >> 5, lane = tid & 31;

    if (i < 1024) {
        // ---------------- feat3: l3 channels, full-res maps ----------------
        int b = b0 + (i >> 6);
        int ct = i & 63;
        {
            const float4* s4 = (const float4*)(maps_out + (size_t)b * LL * HW);
            float4* d4 = (float4*)mp_s;
            for (int k = tid; k < LL * HW / 4; k += 128) d4[k] = s4[k];
        }
        __syncthreads();

        int cl = ct * 16 + warp * 4;
        const float* base = l3 + ((size_t)b * C3 + cl) * HW;

        float acc[4][LL];
        #pragma unroll
        for (int cc = 0; cc < 4; cc++)
            #pragma unroll
            for (int l = 0; l < LL; l++) acc[cc][l] = 0.f;

        #pragma unroll 1
        for (int it = 0; it < 6; it++) {
            int p4 = it * 32 + lane;
            float4 xv[4];
            #pragma unroll
            for (int cc = 0; cc < 4; cc++)
                xv[cc] = ((const float4*)(base + (size_t)cc * HW))[p4];
            #pragma unroll
            for (int l = 0; l < LL; l++) {
                float4 m = ((const float4*)(mp_s + l * HW))[p4];
                #pragma unroll
                for (int cc = 0; cc < 4; cc++) {
                    acc[cc][l] = fmaf(m.x, xv[cc].x, acc[cc][l]);
                    acc[cc][l] = fmaf(m.y, xv[cc].y, acc[cc][l]);
                    acc[cc][l] = fmaf(m.z, xv[cc].z, acc[cc][l]);
                    acc[cc][l] = fmaf(m.w, xv[cc].w, acc[cc][l]);
                }
            }
        }
        if (lane < 4) {                       // tail: float4 idx 192..195
            int p4 = 192 + lane;
            float4 xv[4];
            #pragma unroll
            for (int cc = 0; cc < 4; cc++)
                xv[cc] = ((const float4*)(base + (size_t)cc * HW))[p4];
            #pragma unroll
            for (int l = 0; l < LL; l++) {
                float4 m = ((const float4*)(mp_s + l * HW))[p4];
                #pragma unroll
                for (int cc = 0; cc < 4; cc++) {
                    acc[cc][l] = fmaf(m.x, xv[cc].x, acc[cc][l]);
                    acc[cc][l] = fmaf(m.y, xv[cc].y, acc[cc][l]);
                    acc[cc][l] = fmaf(m.z, xv[cc].z, acc[cc][l]);
                    acc[cc][l] = fmaf(m.w, xv[cc].w, acc[cc][l]);
                }
            }
        }

        #pragma unroll
        for (int off = 16; off; off >>= 1)
            #pragma unroll
            for (int cc = 0; cc < 4; cc++)
                #pragma unroll
                for (int l = 0; l < LL; l++)
                    acc[cc][l] += __shfl_xor_sync(0xffffffffu, acc[cc][l], off);

        if (lane < 4) {
            int c = C4 + cl + lane;
            float mf = 0.f;
            #pragma unroll
            for (int l = 0; l < LL; l++) {
                float v = acc[lane][l] * (1.f / (float)HW);
                af_out[((size_t)b * CTOT + c) * LL + l] = v;
                if (l < LL - 1) mf = fmaf(v, modulation[c * LL + l], mf);
            }
            g_meanf[(size_t)b * CTOT + c] = mf * (1.f / 8.f);
        }

    } else {
        // ---------------- feat4: l4 channels, adjoint maps @14x14 ----------
        int j = i - 1024;
        int b = b0 + (j >> 7);
        int ct = j & 127;
        {
            const float4* s4 = (const float4*)(g_mdown + (size_t)b * LL * HW4);
            float4* d4 = (float4*)mp_s;
            for (int k = tid; k < LL * HW4 / 4; k += 128) d4[k] = s4[k];
        }
        __syncthreads();

        int cl = ct * 16 + warp * 4;
        const float* base = l4 + ((size_t)b * C4 + cl) * HW4;

        float acc[4][LL];
        #pragma unroll
        for (int cc = 0; cc < 4; cc++)
            #pragma unroll
            for (int l = 0; l < LL; l++) acc[cc][l] = 0.f;

        {
            int p4 = lane;                    // 0..31 < 49
            float4 xv[4];
            #pragma unroll
            for (int cc = 0; cc < 4; cc++)
                xv[cc] = ((const float4*)(base + (size_t)cc * HW4))[p4];
            #pragma unroll
            for (int l = 0; l < LL; l++) {
                float4 m = ((const float4*)(mp_s + l * HW4))[p4];
                #pragma unroll
                for (int cc = 0; cc < 4; cc++) {
                    acc[cc][l] = fmaf(m.x, xv[cc].x, acc[cc][l]);
                    acc[cc][l] = fmaf(m.y, xv[cc].y, acc[cc][l]);
                    acc[cc][l] = fmaf(m.z, xv[cc].z, acc[cc][l]);
                    acc[cc][l] = fmaf(m.w, xv[cc].w, acc[cc][l]);
                }
            }
        }
        if (lane < 17) {                      // float4 idx 32..48
            int p4 = 32 + lane;
            float4 xv[4];
            #pragma unroll
            for (int cc = 0; cc < 4; cc++)
                xv[cc] = ((const float4*)(base + (size_t)cc * HW4))[p4];
            #pragma unroll
            for (int l = 0; l < LL; l++) {
                float4 m = ((const float4*)(mp_s + l * HW4))[p4];
                #pragma unroll
                for (int cc = 0; cc < 4; cc++) {
                    acc[cc][l] = fmaf(m.x, xv[cc].x, acc[cc][l]);
                    acc[cc][l] = fmaf(m.y, xv[cc].y, acc[cc][l]);
                    acc[cc][l] = fmaf(m.z, xv[cc].z, acc[cc][l]);
                    acc[cc][l] = fmaf(m.w, xv[cc].w, acc[cc][l]);
                }
            }
        }

        #pragma unroll
        for (int off = 16; off; off >>= 1)
            #pragma unroll
            for (int cc = 0; cc < 4; cc++)
                #pragma unroll
                for (int l = 0; l < LL; l++)
                    acc[cc][l] += __shfl_xor_sync(0xffffffffu, acc[cc][l], off);

        if (lane < 4) {
            int c = cl + lane;
            float mf = 0.f;
            #pragma unroll
            for (int l = 0; l < LL; l++) {
                float v = acc[lane][l] * (1.f / (float)HW);
                af_out[((size_t)b * CTOT + c) * LL + l] = v;
                if (l < LL - 1) mf = fmaf(v, modulation[c * LL + l], mf);
            }
            g_meanf[(size_t)b * CTOT + c] = mf * (1.f / 8.f);
        }
    }
}

// ---------------------------------------------------------------------------
// attr_scores = mean_features @ attr_w^T + attr_b.
__global__ void k_attr(const float* __restrict__ attr_w, const float* __restrict__ attr_b,
                       float* __restrict__ attr_out) {
    int a = blockIdx.x;
    int warp = threadIdx.x >> 5, lane = threadIdx.x & 31;
    const float* wrow = attr_w + (size_t)a * CTOT;
    float acc[8];
    #pragma unroll
    for (int j = 0; j < 8; j++) acc[j] = 0.f;
    for (int k = lane; k < CTOT; k += 32) {
        float wv = wrow[k];
        #pragma unroll
        for (int j = 0; j < 8; j++)
            acc[j] = fmaf(wv, g_meanf[(size_t)(warp * 8 + j) * CTOT + k], acc[j]);
    }
    #pragma unroll
    for (int j = 0; j < 8; j++)
        #pragma unroll
        for (int off = 16; off; off >>= 1)
            acc[j] += __shfl_down_sync(0xffffffffu, acc[j], off);
    if (lane == 0) {
        float bias = attr_b[a];
        #pragma unroll
        for (int j = 0; j < 8; j++)
            attr_out[(size_t)(warp * 8 + j) * NA + a] = acc[j] + bias;
    }
}

// class_scores = attr_scores @ class_w^T
__global__ void k_class(const float* __restrict__ attr_out, const float* __restrict__ class_w,
                        float* __restrict__ class_out) {
    int t = blockIdx.x * 256 + threadIdx.x;
    if (t >= BB * NC) return;
    int b = t / NC, nc = t % NC;
    const float* ar = attr_out + (size_t)b * NA;
    const float* wr = class_w + (size_t)nc * NA;
    float s = 0.f;
    #pragma unroll 4
    for (int k = 0; k < NA; k++) s = fmaf(ar[k], wr[k], s);
    class_out[t] = s;
}

// ---------------------------------------------------------------------------
extern "C" void kernel_launch(void* const* d_in, const int* in_sizes, int n_in,
                              void* d_out, int out_size) {
    const float* l3     = (const float*)d_in[0];
    const float* l4     = (const float*)d_in[1];
    const float* conv_w = (const float*)d_in[2];
    const float* modu   = (const float*)d_in[3];
    const float* attr_w = (const float*)d_in[4];
    const float* attr_b = (const float*)d_in[5];
    const float* class_w= (const float*)d_in[6];

    float* out = (float*)d_out;
    float* attr_out  = out + OFF_ATTR;
    float* class_out = out + OFF_CLASS;
    float* maps_out  = out + OFF_MAPS;
    float* af_out    = out + OFF_AF;

    // Batch-grouped pipeline for L2 reuse: x[group] read from DRAM in k_ab,
    // re-read from L2 in k_feat. 8 launches total.
    for (int g = 0; g < 2; g++) {
        int b0 = g * GB;
        k_ab<<<257, 128>>>(l3, l4, conv_w, b0);
        k_softmax<<<GB, 784>>>(maps_out, b0);
        k_feat<<<3072, 128>>>(l3, l4, maps_out, modu, af_out, b0);
    }
    k_attr<<<NA, 128>>>(attr_w, attr_b, attr_out);
    k_class<<<(BB * NC + 255) / 256, 256>>>(attr_out, class_w, class_out);
}

// round 16
// speedup vs baseline: 1.2570x; 1.2570x over previous
#include <cuda_runtime.h>
#include <math.h>

// Problem constants
#define BB 32
#define C3 1024
#define C4 2048
#define CTOT 3072
#define HH 28
#define HW 784
#define H4 14
#define HW4 196
#define LL 9
#define NA 312
#define NC 200

#define NCH3 16     // l3 channel chunks of 64
#define NCH4 32     // l4 channel chunks of 64
#define RED4_N (BB * LL * HW4 / 4)   // 14112 float4 elems

// Output layout (flattened concat of reference return tuple)
#define OFF_ATTR  0
#define OFF_CLASS (BB*NA)                  // 9984
#define OFF_MAPS  (OFF_CLASS + BB*NC)      // 16384
#define OFF_AF    (OFF_MAPS + BB*LL*HW)    // 242176

// Scratch (__device__ globals; no runtime allocation allowed)
__device__ __align__(16) float g_pab4[NCH4 * BB * LL * HW4];  // l4 partial ab, 14x14
__device__ __align__(16) float g_pab3[NCH3 * BB * LL * HW];   // l3 partial ab, 28x28
__device__ __align__(16) float g_ab4[BB * LL * HW4];          // reduced l4 ab
__device__ __align__(16) float g_mdown[BB * LL * HW4];        // adjoint-downsampled maps
__device__ __align__(16) float g_meanf[BB * CTOT];            // mean features
__device__ float g_asq[LL];

// ---------------------------------------------------------------------------
// Partial ab from l4 on native 14x14 grid. 64-ch chunks, 4-pixel threads.
// grid (13, 32), block 128.
__global__ void __launch_bounds__(128, 5) k_ab4(const float* __restrict__ l4,
                                                const float* __restrict__ conv_w) {
    __shared__ __align__(16) float w_s[LL * 64];
    int ck = blockIdx.y;
    for (int i = threadIdx.x; i < LL * 64; i += 128)
        w_s[i] = conv_w[(i >> 6) * CTOT + ck * 64 + (i & 63)];
    __syncthreads();

    int g = blockIdx.x * 128 + threadIdx.x;
    if (g >= BB * 49) return;
    int b = g / 49;
    int q = (g % 49) * 4;

    const float* src = l4 + ((size_t)b * C4 + (size_t)ck * 64) * HW4 + q;

    float4 acc[LL];
    #pragma unroll
    for (int l = 0; l < LL; l++) acc[l] = make_float4(0.f, 0.f, 0.f, 0.f);

    #pragma unroll 2
    for (int ci = 0; ci < 64; ci += 4) {
        float4 x0 = *(const float4*)(src + (size_t)(ci + 0) * HW4);
        float4 x1 = *(const float4*)(src + (size_t)(ci + 1) * HW4);
        float4 x2 = *(const float4*)(src + (size_t)(ci + 2) * HW4);
        float4 x3 = *(const float4*)(src + (size_t)(ci + 3) * HW4);
        #pragma unroll
        for (int l = 0; l < LL; l++) {
            float4 w = *(const float4*)&w_s[l * 64 + ci];
            acc[l].x = fmaf(w.x, x0.x, acc[l].x);
            acc[l].y = fmaf(w.x, x0.y, acc[l].y);
            acc[l].z = fmaf(w.x, x0.z, acc[l].z);
            acc[l].w = fmaf(w.x, x0.w, acc[l].w);
            acc[l].x = fmaf(w.y, x1.x, acc[l].x);
            acc[l].y = fmaf(w.y, x1.y, acc[l].y);
            acc[l].z = fmaf(w.y, x1.z, acc[l].z);
            acc[l].w = fmaf(w.y, x1.w, acc[l].w);
            acc[l].x = fmaf(w.z, x2.x, acc[l].x);
            acc[l].y = fmaf(w.z, x2.y, acc[l].y);
            acc[l].z = fmaf(w.z, x2.z, acc[l].z);
            acc[l].w = fmaf(w.z, x2.w, acc[l].w);
            acc[l].x = fmaf(w.w, x3.x, acc[l].x);
            acc[l].y = fmaf(w.w, x3.y, acc[l].y);
            acc[l].z = fmaf(w.w, x3.z, acc[l].z);
            acc[l].w = fmaf(w.w, x3.w, acc[l].w);
        }
    }
    #pragma unroll
    for (int l = 0; l < LL; l++)
        *(float4*)&g_pab4[((size_t)(ck * BB + b) * LL + l) * HW4 + q] = acc[l];
}

// ---------------------------------------------------------------------------
// Partial ab from l3 on 28x28 grid. 64-ch chunks, 4-pixel threads.
// grid (50, 16), block 128: x<49 main; x==49: red4 + (y==0) asq.
__global__ void __launch_bounds__(128, 5) k_ab3(const float* __restrict__ l3,
                                                const float* __restrict__ conv_w) {
    __shared__ __align__(16) float s_buf[LL * 64];
    int tid = threadIdx.x;

    if (blockIdx.x == 49) {
        int eid = blockIdx.y;   // 0..15
        const float4* src = (const float4*)g_pab4;
        for (int idx = eid * 128 + tid; idx < RED4_N; idx += 16 * 128) {
            float4 s = make_float4(0.f, 0.f, 0.f, 0.f);
            #pragma unroll
            for (int ck = 0; ck < NCH4; ck++) {
                float4 v = src[(size_t)ck * RED4_N + idx];
                s.x += v.x; s.y += v.y; s.z += v.z; s.w += v.w;
            }
            ((float4*)g_ab4)[idx] = s;
        }
        if (eid == 0) {
            for (int l = 0; l < LL; l++) {
                float s = 0.f;
                for (int c = tid; c < CTOT; c += 128) s += conv_w[l * CTOT + c];
                s_buf[tid] = s;
                __syncthreads();
                for (int off = 64; off; off >>= 1) {
                    if (tid < off) s_buf[tid] += s_buf[tid + off];
                    __syncthreads();
                }
                if (tid == 0) g_asq[l] = s_buf[0];
                __syncthreads();
            }
        }
        return;
    }

    int ck = blockIdx.y;
    for (int i = tid; i < LL * 64; i += 128)
        s_buf[i] = conv_w[(i >> 6) * CTOT + C4 + ck * 64 + (i & 63)];
    __syncthreads();

    int g = blockIdx.x * 128 + tid;   // 0..6271
    int b = g / 196;
    int p = (g % 196) * 4;

    const float* src = l3 + ((size_t)b * C3 + (size_t)ck * 64) * HW + p;

    float4 acc[LL];
    #pragma unroll
    for (int l = 0; l < LL; l++) acc[l] = make_float4(0.f, 0.f, 0.f, 0.f);

    #pragma unroll 2
    for (int ci = 0; ci < 64; ci += 4) {
        float4 x0 = *(const float4*)(src + (size_t)(ci + 0) * HW);
        float4 x1 = *(const float4*)(src + (size_t)(ci + 1) * HW);
        float4 x2 = *(const float4*)(src + (size_t)(ci + 2) * HW);
        float4 x3 = *(const float4*)(src + (size_t)(ci + 3) * HW);
        #pragma unroll
        for (int l = 0; l < LL; l++) {
            float4 w = *(const float4*)&s_buf[l * 64 + ci];
            acc[l].x = fmaf(w.x, x0.x, acc[l].x);
            acc[l].y = fmaf(w.x, x0.y, acc[l].y);
            acc[l].z = fmaf(w.x, x0.z, acc[l].z);
            acc[l].w = fmaf(w.x, x0.w, acc[l].w);
            acc[l].x = fmaf(w.y, x1.x, acc[l].x);
            acc[l].y = fmaf(w.y, x1.y, acc[l].y);
            acc[l].z = fmaf(w.y, x1.z, acc[l].z);
            acc[l].w = fmaf(w.y, x1.w, acc[l].w);
            acc[l].x = fmaf(w.z, x2.x, acc[l].x);
            acc[l].y = fmaf(w.z, x2.y, acc[l].y);
            acc[l].z = fmaf(w.z, x2.z, acc[l].z);
            acc[l].w = fmaf(w.z, x2.w, acc[l].w);
            acc[l].x = fmaf(w.w, x3.x, acc[l].x);
            acc[l].y = fmaf(w.w, x3.y, acc[l].y);
            acc[l].z = fmaf(w.w, x3.z, acc[l].z);
            acc[l].w = fmaf(w.w, x3.w, acc[l].w);
        }
    }
    #pragma unroll
    for (int l = 0; l < LL; l++)
        *(float4*)&g_pab3[((size_t)(ck * BB + b) * LL + l) * HW + p] = acc[l];
}

// ---------------------------------------------------------------------------
// Per-pixel: gather l3 partials, bilinear-upsample reduced l4 ab, softmax.
__global__ void k_softmax(float* __restrict__ maps_out) {
    int t = blockIdx.x * 256 + threadIdx.x;
    int b = t / HW, p = t % HW;
    int y = p / HH, x = p % HH;

    float fy = y * 0.5f - 0.25f;
    int iy = (int)floorf(fy);
    float wy1 = fy - (float)iy;
    float wy0 = 1.f - wy1;
    int y0 = max(iy, 0), y1 = min(iy + 1, H4 - 1);

    float fx = x * 0.5f - 0.25f;
    int ix = (int)floorf(fx);
    float wx1 = fx - (float)ix;
    float wx0 = 1.f - wx1;
    int x0 = max(ix, 0), x1 = min(ix + 1, H4 - 1);

    float logit[LL];
    float mx = -1e30f;
    #pragma unroll
    for (int l = 0; l < LL; l++) {
        const float* a4 = g_ab4 + (size_t)(b * LL + l) * HW4;
        float v = wy0 * (wx0 * a4[y0 * H4 + x0] + wx1 * a4[y0 * H4 + x1])
                + wy1 * (wx0 * a4[y1 * H4 + x0] + wx1 * a4[y1 * H4 + x1]);
        float s3 = 0.f;
        #pragma unroll
        for (int ck = 0; ck < NCH3; ck++)
            s3 += g_pab3[((size_t)(ck * BB + b) * LL + l) * HW + p];
        float lg = 2.f * (v + s3) - g_asq[l];
        logit[l] = lg;
        mx = fmaxf(mx, lg);
    }
    float e[LL], den = 0.f;
    #pragma unroll
    for (int l = 0; l < LL; l++) { e[l] = __expf(logit[l] - mx); den += e[l]; }
    float inv = 1.f / den;
    #pragma unroll
    for (int l = 0; l < LL; l++)
        maps_out[(size_t)(b * LL + l) * HW + p] = e[l] * inv;
}

// ---------------------------------------------------------------------------
// Adjoint bilinear weight: contribution of output index y to input index r.
__device__ __forceinline__ float tapw(int y, int r) {
    float f = y * 0.5f - 0.25f;
    int i0 = (int)floorf(f);
    float w1 = f - (float)i0;
    int c0 = max(i0, 0), c1 = min(i0 + 1, H4 - 1);
    float w = 0.f;
    if (c0 == r) w += 1.f - w1;
    if (c1 == r) w += w1;
    return w;
}

// ---------------------------------------------------------------------------
// all_features for l3 channels (c >= 2048): 4 channels/warp, 32 ch/block.
// grid (33, 32), block 256. x==32 blocks: mdown duty.
__global__ void __launch_bounds__(256, 3)
k_feat3(const float* __restrict__ l3, const float* __restrict__ maps_out,
        const float* __restrict__ modulation, float* __restrict__ af_out) {
    __shared__ __align__(16) float mp_s[LL * HW];   // 28224 B
    int b = blockIdx.y;

    if (blockIdx.x == 32) {
        // ---- extra duty: adjoint-downsample maps for this batch
        for (int t = threadIdx.x; t < LL * HW4; t += 256) {
            int l = t / HW4, q = t % HW4;
            int r = q / H4, c = q % H4;
            const float* mp = maps_out + (size_t)(b * LL + l) * HW;
            int ylo = max(0, 2 * r - 1), yhi = min(HH - 1, 2 * r + 2);
            int xlo = max(0, 2 * c - 1), xhi = min(HH - 1, 2 * c + 2);
            float s = 0.f;
            for (int y = ylo; y <= yhi; y++) {
                float wy = tapw(y, r);
                for (int x = xlo; x <= xhi; x++)
                    s += wy * tapw(x, c) * mp[y * HH + x];
            }
            g_mdown[(size_t)b * LL * HW4 + t] = s;
        }
        return;
    }

    {
        const float4* s4 = (const float4*)(maps_out + (size_t)b * LL * HW);
        float4* d4 = (float4*)mp_s;
        for (int i = threadIdx.x; i < LL * HW / 4; i += 256) d4[i] = s4[i];
    }
    __syncthreads();

    int warp = threadIdx.x >> 5, lane = threadIdx.x & 31;
    int cl = blockIdx.x * 32 + warp * 4;          // 0..1020
    const float* base = l3 + ((size_t)b * C3 + cl) * HW;

    float acc[4][LL];
    #pragma unroll
    for (int cc = 0; cc < 4; cc++)
        #pragma unroll
        for (int l = 0; l < LL; l++) acc[cc][l] = 0.f;

    // 196 float4 per channel row: 6 full warp-iters + 4-lane tail
    #pragma unroll 1
    for (int it = 0; it < 6; it++) {
        int p4 = it * 32 + lane;
        float4 xv[4];
        #pragma unroll
        for (int cc = 0; cc < 4; cc++)
            xv[cc] = ((const float4*)(base + (size_t)cc * HW))[p4];
        #pragma unroll
        for (int l = 0; l < LL; l++) {
            float4 m = ((const float4*)(mp_s + l * HW))[p4];
            #pragma unroll
            for (int cc = 0; cc < 4; cc++) {
                acc[cc][l] = fmaf(m.x, xv[cc].x, acc[cc][l]);
                acc[cc][l] = fmaf(m.y, xv[cc].y, acc[cc][l]);
                acc[cc][l] = fmaf(m.z, xv[cc].z, acc[cc][l]);
                acc[cc][l] = fmaf(m.w, xv[cc].w, acc[cc][l]);
            }
        }
    }
    if (lane < 4) {
        int p4 = 192 + lane;
        float4 xv[4];
        #pragma unroll
        for (int cc = 0; cc < 4; cc++)
            xv[cc] = ((const float4*)(base + (size_t)cc * HW))[p4];
        #pragma unroll
        for (int l = 0; l < LL; l++) {
            float4 m = ((const float4*)(mp_s + l * HW))[p4];
            #pragma unroll
            for (int cc = 0; cc < 4; cc++) {
                acc[cc][l] = fmaf(m.x, xv[cc].x, acc[cc][l]);
                acc[cc][l] = fmaf(m.y, xv[cc].y, acc[cc][l]);
                acc[cc][l] = fmaf(m.z, xv[cc].z, acc[cc][l]);
                acc[cc][l] = fmaf(m.w, xv[cc].w, acc[cc][l]);
            }
        }
    }

    #pragma unroll
    for (int off = 16; off; off >>= 1)
        #pragma unroll
        for (int cc = 0; cc < 4; cc++)
            #pragma unroll
            for (int l = 0; l < LL; l++)
                acc[cc][l] += __shfl_xor_sync(0xffffffffu, acc[cc][l], off);

    if (lane < 4) {
        int c = C4 + cl + lane;
        float mf = 0.f;
        #pragma unroll
        for (int l = 0; l < LL; l++) {
            float v = acc[lane][l] * (1.f / (float)HW);
            af_out[((size_t)b * CTOT + c) * LL + l] = v;
            if (l < LL - 1) mf = fmaf(v, modulation[c * LL + l], mf);
        }
        g_meanf[(size_t)b * CTOT + c] = mf * (1.f / 8.f);
    }
}

// ---------------------------------------------------------------------------
// all_features for l4 channels (c < 2048) via adjoint maps on 14x14.
// 4 channels/warp, 32 ch/block. grid (64, 32), block 256.
__global__ void __launch_bounds__(256, 3)
k_feat4(const float* __restrict__ l4, const float* __restrict__ modulation,
        float* __restrict__ af_out) {
    __shared__ __align__(16) float md_s[LL * HW4];   // 7056 B
    int b = blockIdx.y;
    {
        const float4* s4 = (const float4*)(g_mdown + (size_t)b * LL * HW4);
        float4* d4 = (float4*)md_s;
        for (int i = threadIdx.x; i < LL * HW4 / 4; i += 256) d4[i] = s4[i];
    }
    __syncthreads();

    int warp = threadIdx.x >> 5, lane = threadIdx.x & 31;
    int cl = blockIdx.x * 32 + warp * 4;          // 0..2044
    const float* base = l4 + ((size_t)b * C4 + cl) * HW4;

    float acc[4][LL];
    #pragma unroll
    for (int cc = 0; cc < 4; cc++)
        #pragma unroll
        for (int l = 0; l < LL; l++) acc[cc][l] = 0.f;

    // 49 float4 per channel row: 1 full warp-iter + 17-lane tail
    {
        int p4 = lane;
        float4 xv[4];
        #pragma unroll
        for (int cc = 0; cc < 4; cc++)
            xv[cc] = ((const float4*)(base + (size_t)cc * HW4))[p4];
        #pragma unroll
        for (int l = 0; l < LL; l++) {
            float4 m = ((const float4*)(md_s + l * HW4))[p4];
            #pragma unroll
            for (int cc = 0; cc < 4; cc++) {
                acc[cc][l] = fmaf(m.x, xv[cc].x, acc[cc][l]);
                acc[cc][l] = fmaf(m.y, xv[cc].y, acc[cc][l]);
                acc[cc][l] = fmaf(m.z, xv[cc].z, acc[cc][l]);
                acc[cc][l] = fmaf(m.w, xv[cc].w, acc[cc][l]);
            }
        }
    }
    if (lane < 17) {
        int p4 = 32 + lane;
        float4 xv[4];
        #pragma unroll
        for (int cc = 0; cc < 4; cc++)
            xv[cc] = ((const float4*)(base + (size_t)cc * HW4))[p4];
        #pragma unroll
        for (int l = 0; l < LL; l++) {
            float4 m = ((const float4*)(md_s + l * HW4))[p4];
            #pragma unroll
            for (int cc = 0; cc < 4; cc++) {
                acc[cc][l] = fmaf(m.x, xv[cc].x, acc[cc][l]);
                acc[cc][l] = fmaf(m.y, xv[cc].y, acc[cc][l]);
                acc[cc][l] = fmaf(m.z, xv[cc].z, acc[cc][l]);
                acc[cc][l] = fmaf(m.w, xv[cc].w, acc[cc][l]);
            }
        }
    }

    #pragma unroll
    for (int off = 16; off; off >>= 1)
        #pragma unroll
        for (int cc = 0; cc < 4; cc++)
            #pragma unroll
            for (int l = 0; l < LL; l++)
                acc[cc][l] += __shfl_xor_sync(0xffffffffu, acc[cc][l], off);

    if (lane < 4) {
        int c = cl + lane;
        float mf = 0.f;
        #pragma unroll
        for (int l = 0; l < LL; l++) {
            float v = acc[lane][l] * (1.f / (float)HW);
            af_out[((size_t)b * CTOT + c) * LL + l] = v;
            if (l < LL - 1) mf = fmaf(v, modulation[c * LL + l], mf);
        }
        g_meanf[(size_t)b * CTOT + c] = mf * (1.f / 8.f);
    }
}

// ---------------------------------------------------------------------------
// attr_scores = mean_features @ attr_w^T + attr_b.
__global__ void k_attr(const float* __restrict__ attr_w, const float* __restrict__ attr_b,
                       float* __restrict__ attr_out) {
    int a = blockIdx.x;
    int warp = threadIdx.x >> 5, lane = threadIdx.x & 31;
    const float* wrow = attr_w + (size_t)a * CTOT;
    float acc[8];
    #pragma unroll
    for (int j = 0; j < 8; j++) acc[j] = 0.f;
    for (int k = lane; k < CTOT; k += 32) {
        float wv = wrow[k];
        #pragma unroll
        for (int j = 0; j < 8; j++)
            acc[j] = fmaf(wv, g_meanf[(size_t)(warp * 8 + j) * CTOT + k], acc[j]);
    }
    #pragma unroll
    for (int j = 0; j < 8; j++)
        #pragma unroll
        for (int off = 16; off; off >>= 1)
            acc[j] += __shfl_down_sync(0xffffffffu, acc[j], off);
    if (lane == 0) {
        float bias = attr_b[a];
        #pragma unroll
        for (int j = 0; j < 8; j++)
            attr_out[(size_t)(warp * 8 + j) * NA + a] = acc[j] + bias;
    }
}

// class_scores = attr_scores @ class_w^T
__global__ void k_class(const float* __restrict__ attr_out, const float* __restrict__ class_w,
                        float* __restrict__ class_out) {
    int t = blockIdx.x * 256 + threadIdx.x;
    if (t >= BB * NC) return;
    int b = t / NC, nc = t % NC;
    const float* ar = attr_out + (size_t)b * NA;
    const float* wr = class_w + (size_t)nc * NA;
    float s = 0.f;
    #pragma unroll 4
    for (int k = 0; k < NA; k++) s = fmaf(ar[k], wr[k], s);
    class_out[t] = s;
}

// ---------------------------------------------------------------------------
extern "C" void kernel_launch(void* const* d_in, const int* in_sizes, int n_in,
                              void* d_out, int out_size) {
    const float* l3     = (const float*)d_in[0];
    const float* l4     = (const float*)d_in[1];
    const float* conv_w = (const float*)d_in[2];
    const float* modu   = (const float*)d_in[3];
    const float* attr_w = (const float*)d_in[4];
    const float* attr_b = (const float*)d_in[5];
    const float* class_w= (const float*)d_in[6];

    float* out = (float*)d_out;
    float* attr_out  = out + OFF_ATTR;
    float* class_out = out + OFF_CLASS;
    float* maps_out  = out + OFF_MAPS;
    float* af_out    = out + OFF_AF;

    // Full-batch kernels, 7 launches; k_feat3 is 4th (ncu capture slot).
    k_ab4<<<dim3(13, NCH4), 128>>>(l4, conv_w);
    k_ab3<<<dim3(50, NCH3), 128>>>(l3, conv_w);     // x==49: red4 + asq
    k_softmax<<<98, 256>>>(maps_out);
    k_feat3<<<dim3(33, BB), 256>>>(l3, maps_out, modu, af_out);  // x==32: mdown
    k_feat4<<<dim3(64, BB), 256>>>(l4, modu, af_out);
    k_attr<<<NA, 128>>>(attr_w, attr_b, attr_out);
    k_class<<<(BB * NC + 255) / 256, 256>>>(attr_out, class_w, class_out);
}